// round 5
// baseline (speedup 1.0000x reference)
#include <cuda_runtime.h>
#include <cuda_bf16.h>

// ---------------------------------------------------------------------------
// LinearAttention: B=128, N=196, C=768, h=12, e=64, num_frames=16
//   b = 8, S = 3136, M = 25088 tokens.
// Reshape (B,N)->(b,S) is identity on flattened rows: m = b*S + s.
//
// Stage 1: qkv = x @ W_qkv^T  (fused relu on q,k; scatter to g_q/g_k/g_v)
// Stage 2: kv[b,h,e,d] = sum_s k*v ; k_sum[b,h,e] = sum_s k   (split-K=7)
// Stage 3: out = (q @ kv) / (q . k_sum + eps)
// Stage 4: final = out @ W_proj^T + b_proj
// All fp32 (matches reference bit-closely; rel_err ~1e-6 expected).
// ---------------------------------------------------------------------------

#define MTOK   25088      // 128*196
#define CDIM   768
#define SLEN   3136       // 16*196
#define NBH    96         // b(8) * h(12)
#define KSPLIT 7
#define SCHUNK 448        // 3136/7

__device__ float g_q  [(size_t)MTOK * CDIM];
__device__ float g_k  [(size_t)MTOK * CDIM];
__device__ float g_v  [(size_t)MTOK * CDIM];
__device__ float g_att[(size_t)MTOK * CDIM];
__device__ float g_kvp [NBH * KSPLIT * 64 * 64];
__device__ float g_ksp [NBH * KSPLIT * 64];

// ---------------------------------------------------------------------------
// GEMM core: C[128x64] tile of A(MxK,row) @ Bt(NxK,row)^T, K=768, 256 thr.
// ---------------------------------------------------------------------------

__global__ __launch_bounds__(256)
void qkv_gemm_kernel(const float* __restrict__ A, const float* __restrict__ Bt)
{
    __shared__ float As[16][128];
    __shared__ float Bs[16][64];

    const int t     = threadIdx.x;
    const int mBase = blockIdx.x * 128;
    const int nBase = blockIdx.y * 64;
    const int K     = CDIM;

    const int ar = t >> 2;            // 0..63
    const int ac = (t & 3) << 2;      // 0,4,8,12
    const float* Ap0 = A  + (size_t)(mBase + ar)      * K + ac;
    const float* Ap1 = A  + (size_t)(mBase + ar + 64) * K + ac;
    const float* Bp  = Bt + (size_t)(nBase + ar)      * K + ac;

    const int tx = t & 15;            // n: 4 cols
    const int ty = t >> 4;            // m: 8 rows

    float acc[8][4];
#pragma unroll
    for (int i = 0; i < 8; i++)
#pragma unroll
        for (int j = 0; j < 4; j++) acc[i][j] = 0.f;

    for (int k0 = 0; k0 < K; k0 += 16) {
        float4 a0 = *(const float4*)(Ap0 + k0);
        float4 a1 = *(const float4*)(Ap1 + k0);
        float4 b0 = *(const float4*)(Bp  + k0);
        __syncthreads();
        As[ac + 0][ar]      = a0.x; As[ac + 1][ar]      = a0.y;
        As[ac + 2][ar]      = a0.z; As[ac + 3][ar]      = a0.w;
        As[ac + 0][ar + 64] = a1.x; As[ac + 1][ar + 64] = a1.y;
        As[ac + 2][ar + 64] = a1.z; As[ac + 3][ar + 64] = a1.w;
        Bs[ac + 0][ar] = b0.x; Bs[ac + 1][ar] = b0.y;
        Bs[ac + 2][ar] = b0.z; Bs[ac + 3][ar] = b0.w;
        __syncthreads();
#pragma unroll
        for (int kk = 0; kk < 16; kk++) {
            float4 b4  = ((const float4*)Bs[kk])[tx];
            float4 a40 = ((const float4*)As[kk])[ty * 2];
            float4 a41 = ((const float4*)As[kk])[ty * 2 + 1];
            float av[8] = {a40.x, a40.y, a40.z, a40.w, a41.x, a41.y, a41.z, a41.w};
            float bv[4] = {b4.x, b4.y, b4.z, b4.w};
#pragma unroll
            for (int i = 0; i < 8; i++)
#pragma unroll
                for (int j = 0; j < 4; j++) acc[i][j] += av[i] * bv[j];
        }
    }

    // epilogue: scatter into q/k/v with relu on q,k. 64-wide tiles never
    // straddle the 768 boundary (768 % 64 == 0).
    const int which = nBase / CDIM;                 // 0=q 1=k 2=v
    const int ncol  = (nBase - which * CDIM) + tx * 4;
    float* dst = (which == 0) ? g_q : (which == 1) ? g_k : g_v;
    const bool doRelu = (which < 2);
#pragma unroll
    for (int i = 0; i < 8; i++) {
        const int m = mBase + ty * 8 + i;
        float4 o;
        o.x = doRelu ? fmaxf(acc[i][0], 0.f) : acc[i][0];
        o.y = doRelu ? fmaxf(acc[i][1], 0.f) : acc[i][1];
        o.z = doRelu ? fmaxf(acc[i][2], 0.f) : acc[i][2];
        o.w = doRelu ? fmaxf(acc[i][3], 0.f) : acc[i][3];
        *(float4*)&dst[(size_t)m * CDIM + ncol] = o;
    }
}

__global__ __launch_bounds__(256)
void proj_gemm_kernel(const float* __restrict__ Bt,
                      const float* __restrict__ bias,
                      float* __restrict__ out)
{
    __shared__ float As[16][128];
    __shared__ float Bs[16][64];

    const int t     = threadIdx.x;
    const int mBase = blockIdx.x * 128;
    const int nBase = blockIdx.y * 64;
    const int K     = CDIM;

    const int ar = t >> 2;
    const int ac = (t & 3) << 2;
    const float* Ap0 = g_att + (size_t)(mBase + ar)      * K + ac;
    const float* Ap1 = g_att + (size_t)(mBase + ar + 64) * K + ac;
    const float* Bp  = Bt    + (size_t)(nBase + ar)      * K + ac;

    const int tx = t & 15;
    const int ty = t >> 4;

    float acc[8][4];
#pragma unroll
    for (int i = 0; i < 8; i++)
#pragma unroll
        for (int j = 0; j < 4; j++) acc[i][j] = 0.f;

    for (int k0 = 0; k0 < K; k0 += 16) {
        float4 a0 = *(const float4*)(Ap0 + k0);
        float4 a1 = *(const float4*)(Ap1 + k0);
        float4 b0 = *(const float4*)(Bp  + k0);
        __syncthreads();
        As[ac + 0][ar]      = a0.x; As[ac + 1][ar]      = a0.y;
        As[ac + 2][ar]      = a0.z; As[ac + 3][ar]      = a0.w;
        As[ac + 0][ar + 64] = a1.x; As[ac + 1][ar + 64] = a1.y;
        As[ac + 2][ar + 64] = a1.z; As[ac + 3][ar + 64] = a1.w;
        Bs[ac + 0][ar] = b0.x; Bs[ac + 1][ar] = b0.y;
        Bs[ac + 2][ar] = b0.z; Bs[ac + 3][ar] = b0.w;
        __syncthreads();
#pragma unroll
        for (int kk = 0; kk < 16; kk++) {
            float4 b4  = ((const float4*)Bs[kk])[tx];
            float4 a40 = ((const float4*)As[kk])[ty * 2];
            float4 a41 = ((const float4*)As[kk])[ty * 2 + 1];
            float av[8] = {a40.x, a40.y, a40.z, a40.w, a41.x, a41.y, a41.z, a41.w};
            float bv[4] = {b4.x, b4.y, b4.z, b4.w};
#pragma unroll
            for (int i = 0; i < 8; i++)
#pragma unroll
                for (int j = 0; j < 4; j++) acc[i][j] += av[i] * bv[j];
        }
    }

    const int ncol = nBase + tx * 4;
    const float4 b4 = *(const float4*)&bias[ncol];
#pragma unroll
    for (int i = 0; i < 8; i++) {
        const int m = mBase + ty * 8 + i;
        float4 o;
        o.x = acc[i][0] + b4.x;
        o.y = acc[i][1] + b4.y;
        o.z = acc[i][2] + b4.z;
        o.w = acc[i][3] + b4.w;
        *(float4*)&out[(size_t)m * CDIM + ncol] = o;
    }
}

// ---------------------------------------------------------------------------
// Stage 2: per-(b,h) 64x64 kv = K^T V and k_sum, split-K over s (7 partials).
// grid (96, 7), block 256.
// ---------------------------------------------------------------------------
__global__ __launch_bounds__(256)
void kv_partial_kernel()
{
    __shared__ float ks[16][64];
    __shared__ float vs[16][64];

    const int bh    = blockIdx.x;
    const int b     = bh / 12;
    const int h     = bh - b * 12;
    const int split = blockIdx.y;
    const int s0    = split * SCHUNK;

    const int t  = threadIdx.x;
    const int te = (t & 15) << 2;   // e block
    const int td = (t >> 4) << 2;   // d block

    const float* kbase = g_k + (size_t)b * SLEN * CDIM + h * 64;
    const float* vbase = g_v + (size_t)b * SLEN * CDIM + h * 64;

    const int lrow = t >> 4;        // 0..15 (s within chunk)
    const int lc4  = t & 15;        // float4 col

    float acc[4][4];
#pragma unroll
    for (int i = 0; i < 4; i++)
#pragma unroll
        for (int j = 0; j < 4; j++) acc[i][j] = 0.f;
    float ksum_acc = 0.f;

    for (int c = 0; c < SCHUNK / 16; ++c) {
        const int s = s0 + c * 16;
        __syncthreads();
        ((float4*)ks[lrow])[lc4] =
            *(const float4*)&kbase[(size_t)(s + lrow) * CDIM + lc4 * 4];
        ((float4*)vs[lrow])[lc4] =
            *(const float4*)&vbase[(size_t)(s + lrow) * CDIM + lc4 * 4];
        __syncthreads();

        if (t < 64) {
#pragma unroll
            for (int ss = 0; ss < 16; ss++) ksum_acc += ks[ss][t];
        }
#pragma unroll
        for (int ss = 0; ss < 16; ss++) {
            float4 k4 = ((const float4*)ks[ss])[t & 15];
            float4 v4 = ((const float4*)vs[ss])[t >> 4];
            float kv_[4] = {k4.x, k4.y, k4.z, k4.w};
            float vv_[4] = {v4.x, v4.y, v4.z, v4.w};
#pragma unroll
            for (int i = 0; i < 4; i++)
#pragma unroll
                for (int j = 0; j < 4; j++) acc[i][j] += kv_[i] * vv_[j];
        }
    }

    float* kvdst = g_kvp + ((size_t)bh * KSPLIT + split) * 4096;
#pragma unroll
    for (int i = 0; i < 4; i++) {
        float4 o = {acc[i][0], acc[i][1], acc[i][2], acc[i][3]};
        *(float4*)&kvdst[(te + i) * 64 + td] = o;
    }
    if (t < 64) g_ksp[((size_t)bh * KSPLIT + split) * 64 + t] = ksum_acc;
}

// ---------------------------------------------------------------------------
// Stage 3: out[s, h*64+d] = (q . kv) / (q . k_sum + eps).
// grid (96, 16): block = (b,h) x 196-token slab. 256 thr = 8 warps,
// warp handles one token s at a time; lanes split the 64 d outputs 2-way.
// ---------------------------------------------------------------------------
__global__ __launch_bounds__(256)
void attn_out_kernel()
{
    __shared__ float skv[64][64];   // kv[e][d]
    __shared__ float sks[64];       // k_sum[e]
    __shared__ float sq[8][64];     // per-warp q row staging

    const int bh = blockIdx.x;
    const int b  = bh / 12;
    const int h  = bh - b * 12;
    const int t  = threadIdx.x;

    // reduce the 7 split-K partials while loading smem
    for (int idx = t; idx < 4096; idx += 256) {
        float sum = 0.f;
        const float* p = g_kvp + (size_t)bh * KSPLIT * 4096 + idx;
#pragma unroll
        for (int s = 0; s < KSPLIT; s++) sum += p[(size_t)s * 4096];
        skv[idx >> 6][idx & 63] = sum;
    }
    if (t < 64) {
        float sum = 0.f;
        const float* p = g_ksp + (size_t)bh * KSPLIT * 64 + t;
#pragma unroll
        for (int s = 0; s < KSPLIT; s++) sum += p[(size_t)s * 64];
        sks[t] = sum;
    }
    __syncthreads();

    const int w    = t >> 5;
    const int lane = t & 31;
    const int sBase = blockIdx.y * 196;

    for (int si = w; si < 196; si += 8) {
        const int s = sBase + si;
        const float* qrow = g_q + (size_t)(b * SLEN + s) * CDIM + h * 64;
        float2 q2 = *(const float2*)&qrow[lane * 2];
        sq[w][lane * 2]     = q2.x;
        sq[w][lane * 2 + 1] = q2.y;
        __syncwarp();

        float acc0 = 0.f, acc1 = 0.f, accz = 0.f;
#pragma unroll 8
        for (int e = 0; e < 64; e++) {
            const float qv = sq[w][e];
            acc0 += qv * skv[e][lane];
            acc1 += qv * skv[e][lane + 32];
            accz += qv * sks[e];
        }
        const float z = 1.f / (accz + 1e-4f);
        float* orow = g_att + (size_t)(b * SLEN + s) * CDIM + h * 64;
        orow[lane]      = acc0 * z;
        orow[lane + 32] = acc1 * z;
        __syncwarp();   // protect sq[w] before next iteration's store
    }
}

// ---------------------------------------------------------------------------

extern "C" void kernel_launch(void* const* d_in, const int* in_sizes, int n_in,
                              void* d_out, int out_size)
{
    const float* x     = (const float*)d_in[0];   // (128,196,768)
    const float* Wqkv  = (const float*)d_in[1];   // (2304,768)
    const float* Wproj = (const float*)d_in[2];   // (768,768)
    const float* bproj = (const float*)d_in[3];   // (768)
    float* out = (float*)d_out;

    qkv_gemm_kernel <<<dim3(MTOK / 128, 2304 / 64), 256>>>(x, Wqkv);
    kv_partial_kernel<<<dim3(NBH, KSPLIT),          256>>>();
    attn_out_kernel  <<<dim3(NBH, SLEN / 196),      256>>>();
    proj_gemm_kernel <<<dim3(MTOK / 128, CDIM / 64), 256>>>(Wproj, bproj, out);
}

// round 13
// speedup vs baseline: 2.7081x; 2.7081x over previous
#include <cuda_runtime.h>
#include <cstdint>

// ---------------------------------------------------------------------------
// LinearAttention: B=128, N=196, C=768, h=12, e=64, num_frames=16
//   b = 8, S = 3136, M = 25088 tokens.  (B,N)->(b,S) reshape is row-identity.
//
// Stage 1: qkv = x @ W_qkv^T          -> tf32 mma.sync GEMM, relu+scatter epi
// Stage 2: kv[b,h,e,d], k_sum[b,h,e]  -> fp32 SIMT split-K (small: 2.5 GF)
// Stage 3: out = (q.kv)/(q.k_sum+eps) -> fp32 SIMT
// Stage 4: final = out @ W_proj^T + b -> tf32 mma.sync GEMM, bias epi
//
// NOTE: the bench toolchain emits PTX for plain sm_103 (no 'a' feature
// target), so tcgen05/TMEM instructions are rejected by ptxas. mma.sync
// (baseline PTX, sm_80+) is the fastest tensor-core path available here.
// ---------------------------------------------------------------------------

#define MTOK   25088
#define CDIM   768
#define SLEN   3136
#define NBH    96
#define KSPLIT 7
#define SCHUNK 448

__device__ float g_q  [(size_t)MTOK * CDIM];
__device__ float g_k  [(size_t)MTOK * CDIM];
__device__ float g_v  [(size_t)MTOK * CDIM];
__device__ float g_att[(size_t)MTOK * CDIM];
__device__ float g_kvp [NBH * KSPLIT * 64 * 64];
__device__ float g_ksp [NBH * KSPLIT * 64];

__device__ __forceinline__ uint32_t f32_to_tf32(float f) {
    uint32_t r;
    asm("cvt.rna.tf32.f32 %0, %1;" : "=r"(r) : "f"(f));
    return r;
}

// D += A(16x8,row) x B(8x8,col) in tf32, f32 accum.
__device__ __forceinline__ void mma_tf32(float c[4],
                                         const uint32_t a[4],
                                         const uint32_t b[2])
{
    asm volatile(
        "mma.sync.aligned.m16n8k8.row.col.f32.tf32.tf32.f32 "
        "{%0,%1,%2,%3}, {%4,%5,%6,%7}, {%8,%9}, {%0,%1,%2,%3};\n"
        : "+f"(c[0]), "+f"(c[1]), "+f"(c[2]), "+f"(c[3])
        : "r"(a[0]), "r"(a[1]), "r"(a[2]), "r"(a[3]),
          "r"(b[0]), "r"(b[1]));
}

// ---------------------------------------------------------------------------
// tf32 GEMM: C[128 x 128] tile of A(MxK,row) @ Bt(NxK,row)^T, K = 768.
// 256 thr = 8 warps (2 m x 4 n); warp = 64x32 via 4x4 m16n8k8 frags.
// Smem rows padded to 36 words -> conflict-free frag loads & fill stores.
// mode 0: qkv epilogue (relu on q,k; scatter to g_q/g_k/g_v)
// mode 1: proj epilogue (+bias -> out)
// ---------------------------------------------------------------------------
#define KCHUNK 32
#define NCHUNK (CDIM / KCHUNK)   // 24
#define SPAD   36

__global__ __launch_bounds__(256, 2)
void mma_gemm_kernel(const float* __restrict__ A, const float* __restrict__ Bt,
                     const float* __restrict__ bias, float* __restrict__ out,
                     int mode)
{
    __shared__ uint32_t As[128][SPAD];   // [m][k], 32 valid k cols
    __shared__ uint32_t Bs[128][SPAD];   // [n][k]

    const int t     = threadIdx.x;
    const int mBase = blockIdx.x * 128;
    const int nBase = blockIdx.y * 128;

    const float* Ap = A ? A : g_att;     // proj reads the attention output

    const int wid  = t >> 5;
    const int lane = t & 31;
    const int g    = lane >> 2;          // group id 0..7
    const int tig  = lane & 3;           // thread-in-group
    const int wm   = (wid >> 2) * 64;    // warp m offset
    const int wn   = (wid & 3) * 32;     // warp n offset

    float acc[4][4][4];
#pragma unroll
    for (int i = 0; i < 4; i++)
#pragma unroll
        for (int j = 0; j < 4; j++)
#pragma unroll
            for (int r = 0; r < 4; r++) acc[i][j][r] = 0.f;

    for (int c = 0; c < NCHUNK; ++c) {
        const float* Ab = Ap + (size_t)mBase * CDIM + c * KCHUNK;
        const float* Bb = Bt + (size_t)nBase * CDIM + c * KCHUNK;

        __syncthreads();                 // protect smem reuse from prev chunk
#pragma unroll
        for (int i = 0; i < 4; i++) {
            const int idx = t + i * 256;
            const int row = idx >> 3, k4 = idx & 7;
            float4 va = *(const float4*)(Ab + (size_t)row * CDIM + k4 * 4);
            uint4 ta = { f32_to_tf32(va.x), f32_to_tf32(va.y),
                         f32_to_tf32(va.z), f32_to_tf32(va.w) };
            *(uint4*)&As[row][k4 * 4] = ta;
            float4 vb = *(const float4*)(Bb + (size_t)row * CDIM + k4 * 4);
            uint4 tb = { f32_to_tf32(vb.x), f32_to_tf32(vb.y),
                         f32_to_tf32(vb.z), f32_to_tf32(vb.w) };
            *(uint4*)&Bs[row][k4 * 4] = tb;
        }
        __syncthreads();

#pragma unroll
        for (int ks = 0; ks < 4; ks++) {
            const int k0 = ks * 8;
            uint32_t afr[4][4];
#pragma unroll
            for (int mt = 0; mt < 4; mt++) {
                const int r0 = wm + mt * 16 + g;
                afr[mt][0] = As[r0][k0 + tig];
                afr[mt][1] = As[r0 + 8][k0 + tig];
                afr[mt][2] = As[r0][k0 + tig + 4];
                afr[mt][3] = As[r0 + 8][k0 + tig + 4];
            }
            uint32_t bfr[4][2];
#pragma unroll
            for (int nt = 0; nt < 4; nt++) {
                const int rn = wn + nt * 8 + g;
                bfr[nt][0] = Bs[rn][k0 + tig];
                bfr[nt][1] = Bs[rn][k0 + tig + 4];
            }
#pragma unroll
            for (int mt = 0; mt < 4; mt++)
#pragma unroll
                for (int nt = 0; nt < 4; nt++)
                    mma_tf32(acc[mt][nt], afr[mt], bfr[nt]);
        }
    }

    // Epilogue. 128-wide n-tiles never straddle the 768 boundary (768%128==0).
    if (mode == 0) {
        const int which = nBase / CDIM;            // 0=q 1=k 2=v
        float* dst = (which == 0) ? g_q : (which == 1) ? g_k : g_v;
        const int lcolBase = nBase - which * CDIM;
        const bool doRelu = (which < 2);
#pragma unroll
        for (int mt = 0; mt < 4; mt++) {
#pragma unroll
            for (int nt = 0; nt < 4; nt++) {
                const int row0 = mBase + wm + mt * 16 + g;
                const int col  = lcolBase + wn + nt * 8 + tig * 2;
                float2 v01 = { acc[mt][nt][0], acc[mt][nt][1] };
                float2 v23 = { acc[mt][nt][2], acc[mt][nt][3] };
                if (doRelu) {
                    v01.x = fmaxf(v01.x, 0.f); v01.y = fmaxf(v01.y, 0.f);
                    v23.x = fmaxf(v23.x, 0.f); v23.y = fmaxf(v23.y, 0.f);
                }
                *(float2*)&dst[(size_t)row0 * CDIM + col]       = v01;
                *(float2*)&dst[(size_t)(row0 + 8) * CDIM + col] = v23;
            }
        }
    } else {
#pragma unroll
        for (int mt = 0; mt < 4; mt++) {
#pragma unroll
            for (int nt = 0; nt < 4; nt++) {
                const int row0 = mBase + wm + mt * 16 + g;
                const int col  = nBase + wn + nt * 8 + tig * 2;
                const float2 b2 = *(const float2*)&bias[col];
                float2 v01 = { acc[mt][nt][0] + b2.x, acc[mt][nt][1] + b2.y };
                float2 v23 = { acc[mt][nt][2] + b2.x, acc[mt][nt][3] + b2.y };
                *(float2*)&out[(size_t)row0 * CDIM + col]       = v01;
                *(float2*)&out[(size_t)(row0 + 8) * CDIM + col] = v23;
            }
        }
    }
}

// ---------------------------------------------------------------------------
// Stage 2: per-(b,h) 64x64 kv = K^T V and k_sum, split-K over s (7 partials).
// ---------------------------------------------------------------------------
__global__ __launch_bounds__(256)
void kv_partial_kernel()
{
    __shared__ float ks[16][64];
    __shared__ float vs[16][64];

    const int bh    = blockIdx.x;
    const int b     = bh / 12;
    const int h     = bh - b * 12;
    const int split = blockIdx.y;
    const int s0    = split * SCHUNK;

    const int t  = threadIdx.x;
    const int te = (t & 15) << 2;
    const int td = (t >> 4) << 2;

    const float* kbase = g_k + (size_t)b * SLEN * CDIM + h * 64;
    const float* vbase = g_v + (size_t)b * SLEN * CDIM + h * 64;

    const int lrow = t >> 4;
    const int lc4  = t & 15;

    float acc[4][4];
#pragma unroll
    for (int i = 0; i < 4; i++)
#pragma unroll
        for (int j = 0; j < 4; j++) acc[i][j] = 0.f;
    float ksum_acc = 0.f;

    for (int c = 0; c < SCHUNK / 16; ++c) {
        const int s = s0 + c * 16;
        __syncthreads();
        ((float4*)ks[lrow])[lc4] =
            *(const float4*)&kbase[(size_t)(s + lrow) * CDIM + lc4 * 4];
        ((float4*)vs[lrow])[lc4] =
            *(const float4*)&vbase[(size_t)(s + lrow) * CDIM + lc4 * 4];
        __syncthreads();

        if (t < 64) {
#pragma unroll
            for (int ss = 0; ss < 16; ss++) ksum_acc += ks[ss][t];
        }
#pragma unroll
        for (int ss = 0; ss < 16; ss++) {
            float4 k4 = ((const float4*)ks[ss])[t & 15];
            float4 v4 = ((const float4*)vs[ss])[t >> 4];
            float kv_[4] = {k4.x, k4.y, k4.z, k4.w};
            float vv_[4] = {v4.x, v4.y, v4.z, v4.w};
#pragma unroll
            for (int i = 0; i < 4; i++)
#pragma unroll
                for (int j = 0; j < 4; j++) acc[i][j] += kv_[i] * vv_[j];
        }
    }

    float* kvdst = g_kvp + ((size_t)bh * KSPLIT + split) * 4096;
#pragma unroll
    for (int i = 0; i < 4; i++) {
        float4 o = {acc[i][0], acc[i][1], acc[i][2], acc[i][3]};
        *(float4*)&kvdst[(te + i) * 64 + td] = o;
    }
    if (t < 64) g_ksp[((size_t)bh * KSPLIT + split) * 64 + t] = ksum_acc;
}

// ---------------------------------------------------------------------------
// Stage 3: out[s, h*64+d] = (q . kv) / (q . k_sum + eps).
// ---------------------------------------------------------------------------
__global__ __launch_bounds__(256)
void attn_out_kernel()
{
    __shared__ float skv[64][64];
    __shared__ float sks[64];
    __shared__ float sq[8][64];

    const int bh = blockIdx.x;
    const int b  = bh / 12;
    const int h  = bh - b * 12;
    const int t  = threadIdx.x;

    for (int idx = t; idx < 4096; idx += 256) {
        float sum = 0.f;
        const float* p = g_kvp + (size_t)bh * KSPLIT * 4096 + idx;
#pragma unroll
        for (int s = 0; s < KSPLIT; s++) sum += p[(size_t)s * 4096];
        skv[idx >> 6][idx & 63] = sum;
    }
    if (t < 64) {
        float sum = 0.f;
        const float* p = g_ksp + (size_t)bh * KSPLIT * 64 + t;
#pragma unroll
        for (int s = 0; s < KSPLIT; s++) sum += p[(size_t)s * 64];
        sks[t] = sum;
    }
    __syncthreads();

    const int w    = t >> 5;
    const int lane = t & 31;
    const int sBase = blockIdx.y * 196;

    for (int si = w; si < 196; si += 8) {
        const int s = sBase + si;
        const float* qrow = g_q + (size_t)(b * SLEN + s) * CDIM + h * 64;
        float2 q2 = *(const float2*)&qrow[lane * 2];
        sq[w][lane * 2]     = q2.x;
        sq[w][lane * 2 + 1] = q2.y;
        __syncwarp();

        float acc0 = 0.f, acc1 = 0.f, accz = 0.f;
#pragma unroll 8
        for (int e = 0; e < 64; e++) {
            const float qv = sq[w][e];
            acc0 += qv * skv[e][lane];
            acc1 += qv * skv[e][lane + 32];
            accz += qv * sks[e];
        }
        const float z = 1.f / (accz + 1e-4f);
        float* orow = g_att + (size_t)(b * SLEN + s) * CDIM + h * 64;
        orow[lane]      = acc0 * z;
        orow[lane + 32] = acc1 * z;
        __syncwarp();
    }
}

// ---------------------------------------------------------------------------

extern "C" void kernel_launch(void* const* d_in, const int* in_sizes, int n_in,
                              void* d_out, int out_size)
{
    const float* x     = (const float*)d_in[0];   // (128,196,768)
    const float* Wqkv  = (const float*)d_in[1];   // (2304,768)
    const float* Wproj = (const float*)d_in[2];   // (768,768)
    const float* bproj = (const float*)d_in[3];   // (768)
    float* out = (float*)d_out;

    mma_gemm_kernel <<<dim3(MTOK / 128, 2304 / 128), 256>>>(x, Wqkv, nullptr, nullptr, 0);
    kv_partial_kernel<<<dim3(NBH, KSPLIT),           256>>>();
    attn_out_kernel  <<<dim3(NBH, SLEN / 196),       256>>>();
    mma_gemm_kernel <<<dim3(MTOK / 128, CDIM / 128), 256>>>(nullptr, Wproj, bproj, out, 1);
}